// round 5
// baseline (speedup 1.0000x reference)
#include <cuda_runtime.h>
#include <cstdint>

#define H 8
#define B 4
#define S 2048
#define D 8
#define F 64
#define HB 32
#define TILES 64
#define ROWS_CTA 32      // S / TILES

typedef unsigned long long u64;

// Scratch (static __device__, no allocation). q/k/v laid out [hb][d][s].
__device__ float g_q [HB * D * S];        // pre-scaled by log2e/sqrt(8)
__device__ float g_kT[HB * D * S];
__device__ float g_vT[HB * D * S];
__device__ float g_cs  [HB * TILES * S];  // per-(hb,tile) weight column sums
__device__ float g_part[HB * D];          // per-hb head sums

__device__ __forceinline__ float ex2f(float x) {
    float y; asm("ex2.approx.ftz.f32 %0, %1;" : "=f"(y) : "f"(x)); return y;
}
__device__ __forceinline__ u64 fma2(u64 a, u64 b, u64 c) {
    u64 d; asm("fma.rn.f32x2 %0, %1, %2, %3;" : "=l"(d) : "l"(a), "l"(b), "l"(c)); return d;
}
__device__ __forceinline__ u64 mul2u(u64 a, u64 b) {
    u64 d; asm("mul.rn.f32x2 %0, %1, %2;" : "=l"(d) : "l"(a), "l"(b)); return d;
}
__device__ __forceinline__ u64 add2u(u64 a, u64 b) {
    u64 d; asm("add.rn.f32x2 %0, %1, %2;" : "=l"(d) : "l"(a), "l"(b)); return d;
}
__device__ __forceinline__ u64 pack2(float lo, float hi) {
    u64 d; asm("mov.b64 %0, {%1, %2};" : "=l"(d) : "f"(lo), "f"(hi)); return d;
}
__device__ __forceinline__ float2 unpk2(u64 a) {
    float2 r; asm("mov.b64 {%0, %1}, %2;" : "=f"(r.x), "=f"(r.y) : "l"(a)); return r;
}

// ---------------------------------------------------------------------------
// Kernel 1: QKV projection. grid 512 x 192 thr; 16 rows/block.
// Per-thread W column in registers; x rows staged in smem.
// Outputs [hb][d][s]; q pre-scaled by log2e/sqrt(8).
// ---------------------------------------------------------------------------
#define K1_ROWS 16
__global__ void __launch_bounds__(192) qkv_kernel(
    const float* __restrict__ x,
    const float* __restrict__ Wq,
    const float* __restrict__ Wk,
    const float* __restrict__ Wv)
{
    __shared__ float xs[K1_ROWS * 64];
    const int tid = threadIdx.x;
    const int rowbase = blockIdx.x * K1_ROWS;

    for (int i = tid; i < K1_ROWS * 64; i += 192)
        xs[i] = x[(size_t)rowbase * 64 + i];

    const int tensor = tid / 64;
    const int c = tid % 64;
    const int h = c >> 3, d = c & 7;
    const float* W = (tensor == 0) ? Wq : ((tensor == 1) ? Wk : Wv);

    float w[64];
#pragma unroll
    for (int f = 0; f < 64; ++f) w[f] = __ldg(&W[((size_t)h * 64 + f) * 8 + d]);

    __syncthreads();

    float acc[K1_ROWS];
#pragma unroll
    for (int r = 0; r < K1_ROWS; ++r) acc[r] = 0.f;

#pragma unroll
    for (int f4 = 0; f4 < 16; ++f4) {
#pragma unroll
        for (int r = 0; r < K1_ROWS; ++r) {
            float4 xv = *(const float4*)&xs[r * 64 + f4 * 4];  // broadcast
            acc[r] = fmaf(xv.x, w[4*f4+0], fmaf(xv.y, w[4*f4+1],
                     fmaf(xv.z, w[4*f4+2], fmaf(xv.w, w[4*f4+3], acc[r]))));
        }
    }

    const int b  = rowbase >> 11;
    const int s0 = rowbase & 2047;
    const int hb = h * 4 + b;
    const float QS = 0.51006975f;  // log2(e)/sqrt(8)
    float* dst;
    if (tensor == 0) {
        dst = g_q + ((size_t)hb * 8 + d) * S + s0;
#pragma unroll
        for (int i = 0; i < K1_ROWS / 4; ++i)
            *(float4*)(dst + 4 * i) = make_float4(acc[4*i]*QS, acc[4*i+1]*QS,
                                                  acc[4*i+2]*QS, acc[4*i+3]*QS);
    } else {
        dst = (tensor == 1 ? g_kT : g_vT) + ((size_t)hb * 8 + d) * S + s0;
#pragma unroll
        for (int i = 0; i < K1_ROWS / 4; ++i)
            *(float4*)(dst + 4 * i) = make_float4(acc[4*i], acc[4*i+1],
                                                  acc[4*i+2], acc[4*i+3]);
    }
}

// ---------------------------------------------------------------------------
// Kernel 2: attention weights, chunk-major (k in registers).
// grid (TILES=64, HB=32), 256 threads (8 warps), smem ~68.7KB -> 2 CTAs/SM.
// Warp w owns column chunks {2w, 2w+1} (128 cols each) for ALL 32 rows:
//   pass 1: k chunk -> 32 regs once; stream q rows (broadcast LDS), compute
//           exp2 row-partials ls[32] in regs; cross-warp reduce -> invS.
//   pass 2: same loop, recompute exp2, scale by inv, stream fp32 weights
//           (__stcs) and accumulate this warp's column sums (no x-warp reduce).
// ---------------------------------------------------------------------------
__global__ void __launch_bounds__(256, 2) attn_kernel(float* __restrict__ wout)
{
    extern __shared__ float sm[];
    float* kS   = sm;                        // 16384 floats (64KB)
    u64*   q2S  = (u64*)(sm + 16384);        // 32 rows x 8 d  ({q,q} packed, 2KB)
    float* lsS  = sm + 16384 + 512;          // 8 warps x 32 rows (1KB)
    float* invS = lsS + 256;                 // 32 floats

    const int tid  = threadIdx.x;
    const int lane = tid & 31;
    const int wrp  = tid >> 5;
    const int tile = blockIdx.x;
    const int hb   = blockIdx.y;

    {
        const float4* k4 = (const float4*)(g_kT + (size_t)hb * D * S);
        float4* kd = (float4*)kS;
#pragma unroll
        for (int i = 0; i < 16; ++i) kd[tid + 256 * i] = k4[tid + 256 * i];
        // q2S[r][d] = {q,q}
        const int d = tid & 7, r = tid >> 3;
        float q = g_q[((size_t)hb * 8 + d) * S + tile * ROWS_CTA + r];
        q2S[r * 8 + d] = pack2(q, q);
    }
    __syncthreads();

    // ---------------- pass 1: row sums ----------------
    float ls[ROWS_CTA];
#pragma unroll
    for (int r = 0; r < ROWS_CTA; ++r) ls[r] = 0.f;

#pragma unroll
    for (int ci = 0; ci < 2; ++ci) {
        const int col = (wrp * 2 + ci) * 128 + lane * 4;
        u64 k2[8][2];
#pragma unroll
        for (int d = 0; d < 8; ++d) {
            ulonglong2 t = *(const ulonglong2*)(kS + d * S + col);
            k2[d][0] = t.x; k2[d][1] = t.y;
        }
#pragma unroll
        for (int r = 0; r < ROWS_CTA; ++r) {
            u64 q2[8];
#pragma unroll
            for (int j = 0; j < 4; ++j) {
                ulonglong2 t = *(const ulonglong2*)(q2S + r * 8 + j * 2);
                q2[2*j] = t.x; q2[2*j+1] = t.y;
            }
            u64 e[2];
#pragma unroll
            for (int p = 0; p < 2; ++p) {
                u64 s2 = mul2u(q2[0], k2[0][p]);
#pragma unroll
                for (int d = 1; d < 8; ++d) s2 = fma2(q2[d], k2[d][p], s2);
                float2 sv = unpk2(s2);
                e[p] = pack2(ex2f(sv.x), ex2f(sv.y));
            }
            float2 t0 = unpk2(add2u(e[0], e[1]));
            ls[r] += t0.x + t0.y;
        }
    }

    // warp-reduce each row, publish, combine across warps
#pragma unroll
    for (int r = 0; r < ROWS_CTA; ++r) {
        float v = ls[r];
#pragma unroll
        for (int o = 16; o > 0; o >>= 1) v += __shfl_xor_sync(0xffffffffu, v, o);
        if (lane == r) lsS[wrp * ROWS_CTA + r] = v;
    }
    __syncthreads();
    if (tid < ROWS_CTA) {
        float s = 0.f;
#pragma unroll
        for (int w = 0; w < 8; ++w) s += lsS[w * ROWS_CTA + tid];
        invS[tid] = 1.0f / s;
    }
    __syncthreads();

    // ---------------- pass 2: recompute, normalize, write, colsum ----------
#pragma unroll
    for (int ci = 0; ci < 2; ++ci) {
        const int col = (wrp * 2 + ci) * 128 + lane * 4;
        u64 k2[8][2];
#pragma unroll
        for (int d = 0; d < 8; ++d) {
            ulonglong2 t = *(const ulonglong2*)(kS + d * S + col);
            k2[d][0] = t.x; k2[d][1] = t.y;
        }
        u64 cs0 = 0ull, cs1 = 0ull;
        float* wbase = wout + ((size_t)hb * S + (size_t)tile * ROWS_CTA) * S + col;

#pragma unroll 4
        for (int r = 0; r < ROWS_CTA; ++r) {
            u64 q2[8];
#pragma unroll
            for (int j = 0; j < 4; ++j) {
                ulonglong2 t = *(const ulonglong2*)(q2S + r * 8 + j * 2);
                q2[2*j] = t.x; q2[2*j+1] = t.y;
            }
            const float iv = invS[r];
            const u64 iv2 = pack2(iv, iv);
            u64 w2[2];
#pragma unroll
            for (int p = 0; p < 2; ++p) {
                u64 s2 = mul2u(q2[0], k2[0][p]);
#pragma unroll
                for (int d = 1; d < 8; ++d) s2 = fma2(q2[d], k2[d][p], s2);
                float2 sv = unpk2(s2);
                u64 e2 = pack2(ex2f(sv.x), ex2f(sv.y));
                w2[p] = mul2u(e2, iv2);
            }
            cs0 = add2u(cs0, w2[0]);
            cs1 = add2u(cs1, w2[1]);
            float2 a = unpk2(w2[0]);
            float2 b = unpk2(w2[1]);
            __stcs((float4*)(wbase + (size_t)r * S), make_float4(a.x, a.y, b.x, b.y));
        }

        float2 c0 = unpk2(cs0), c1 = unpk2(cs1);
        *(float4*)(g_cs + ((size_t)hb * TILES + tile) * S + col) =
            make_float4(c0.x, c0.y, c1.x, c1.y);
    }
}

// ---------------------------------------------------------------------------
// Kernel 3: per-hb: cs_total[t] = sum_tile g_cs; head_sum[d] = sum_t cs*v[d][t]
// ---------------------------------------------------------------------------
__global__ void __launch_bounds__(256) colsum_v_kernel()
{
    const int hb  = blockIdx.x;
    const int tid = threadIdx.x;
    const int lane = tid & 31, wrp = tid >> 5;
    const int t0 = tid * 8;

    float cs[8];
#pragma unroll
    for (int i = 0; i < 8; ++i) cs[i] = 0.f;
#pragma unroll 1
    for (int tl = 0; tl < TILES; ++tl) {
        const float* src = g_cs + ((size_t)hb * TILES + tl) * S + t0;
        float4 a = *(const float4*)(src);
        float4 b = *(const float4*)(src + 4);
        cs[0]+=a.x; cs[1]+=a.y; cs[2]+=a.z; cs[3]+=a.w;
        cs[4]+=b.x; cs[5]+=b.y; cs[6]+=b.z; cs[7]+=b.w;
    }

    float p[8];
#pragma unroll
    for (int d = 0; d < 8; ++d) {
        const float* vr = g_vT + ((size_t)hb * 8 + d) * S + t0;
        float4 a = *(const float4*)(vr);
        float4 b = *(const float4*)(vr + 4);
        p[d] = cs[0]*a.x + cs[1]*a.y + cs[2]*a.z + cs[3]*a.w
             + cs[4]*b.x + cs[5]*b.y + cs[6]*b.z + cs[7]*b.w;
    }

    __shared__ float red[8][8];
#pragma unroll
    for (int d = 0; d < 8; ++d) {
        float v = p[d];
#pragma unroll
        for (int o = 16; o > 0; o >>= 1) v += __shfl_xor_sync(0xffffffffu, v, o);
        p[d] = v;
    }
    if (lane == 0) {
#pragma unroll
        for (int d = 0; d < 8; ++d) red[wrp][d] = p[d];
    }
    __syncthreads();
    if (tid < 8) {
        float s = 0.f;
#pragma unroll
        for (int w = 0; w < 8; ++w) s += red[w][tid];
        g_part[hb * 8 + tid] = s;
    }
}

// ---------------------------------------------------------------------------
// Kernel 4: out[b][f] = sum_{h,d} head_sum[b][h*8+d] * Wo[h*8+d][f]
// ---------------------------------------------------------------------------
__global__ void __launch_bounds__(256) out_kernel(
    const float* __restrict__ Wo, float* __restrict__ out)
{
    __shared__ float hs[256];
    const int t = threadIdx.x;
    {
        const int b = t >> 6, j = t & 63;
        const int h = j >> 3, d = j & 7;
        hs[t] = g_part[(h * 4 + b) * 8 + d];
    }
    __syncthreads();
    const int b = t >> 6, f = t & 63;
    float a = 0.f;
#pragma unroll
    for (int j = 0; j < 64; ++j)
        a = fmaf(hs[b * 64 + j], Wo[j * 64 + f], a);
    out[b * 64 + f] = a;
}

// ---------------------------------------------------------------------------
extern "C" void kernel_launch(void* const* d_in, const int* in_sizes, int n_in,
                              void* d_out, int out_size)
{
    const float* x  = (const float*)d_in[0];
    const float* Wq = (const float*)d_in[1];
    const float* Wk = (const float*)d_in[2];
    const float* Wv = (const float*)d_in[3];
    const float* Wo = (const float*)d_in[4];
    float* out = (float*)d_out;

    const long long WELEMS = (long long)HB * S * S;  // 134217728
    float* wout = out;
    bool has_sum = false;
    if ((long long)out_size >= WELEMS + 256) {  // [sum(256) | weights]
        wout = out + 256;
        has_sum = true;
    }

    const int k2_smem = 16384 * 4 + 256 * 8 + 256 * 4 + 32 * 4;  // 68736
    cudaFuncSetAttribute(attn_kernel, cudaFuncAttributeMaxDynamicSharedMemorySize, k2_smem);

    qkv_kernel<<<(B * S) / K1_ROWS, 192>>>(x, Wq, Wk, Wv);
    attn_kernel<<<dim3(TILES, HB), 256, k2_smem>>>(wout);
    if (has_sum) {
        colsum_v_kernel<<<HB, 256>>>();
        out_kernel<<<1, 256>>>(Wo, out);
    }
}